// round 15
// baseline (speedup 1.0000x reference)
#include <cuda_runtime.h>
#include <cuda_bf16.h>
#include <cuda_fp16.h>
#include <math.h>
#include <stdint.h>

#define NN 20000
#define NNPAD 20096          // 157 * 128
#define EE 640000
#define HH 4
#define FDIM 256
#define BCAP 128             // edge bucket capacity per node
#define NHALF_ROWS 10112     // 79 * 128 (gemm row-block aligned split)

// ---------------- scratch ----------------------------------------------------
__device__ __half g_xhh[NN * FDIM];    // layer-1 fp16 features
__device__ __half g_xhh2[NN * FDIM];   // layer-2 fp16 features
__device__ float g_as[NN * HH];        // layer-1 alpha_src
__device__ float g_ad[NN * HH];
__device__ float g_as2[NN * HH];       // layer-2 (separate: overlap-safe)
__device__ float g_ad2[NN * HH];
__device__ float g_aek[HH];
__device__ float g_aek2[HH];
__device__ int    g_cursor[NN];
__device__ int4   g_ebkt[(size_t)NN * BCAP];       // {src, eorig, eattr, eatten}
__device__ __nv_bfloat16 g_A3[(size_t)NNPAD * 512];  // [Ah|Al] row stride 2K
__device__ __nv_bfloat16 g_B3[768 * 256];
__device__ __nv_bfloat16 g_B3b[768 * 256];

// ---------------- helpers ----------------------------------------------------
__device__ __forceinline__ uint32_t smem_u32(const void* p) {
    uint32_t a;
    asm("{ .reg .u64 t; cvta.to.shared.u64 t, %1; cvt.u32.u64 %0, t; }" : "=r"(a) : "l"(p));
    return a;
}
__device__ __forceinline__ void ldsm_x4(uint32_t addr, uint32_t& r0, uint32_t& r1,
                                        uint32_t& r2, uint32_t& r3) {
    asm volatile("ldmatrix.sync.aligned.m8n8.x4.shared.b16 {%0,%1,%2,%3}, [%4];"
                 : "=r"(r0), "=r"(r1), "=r"(r2), "=r"(r3) : "r"(addr));
}
__device__ __forceinline__ void ldsm_x4t(uint32_t addr, uint32_t& r0, uint32_t& r1,
                                         uint32_t& r2, uint32_t& r3) {
    asm volatile("ldmatrix.sync.aligned.m8n8.x4.trans.shared.b16 {%0,%1,%2,%3}, [%4];"
                 : "=r"(r0), "=r"(r1), "=r"(r2), "=r"(r3) : "r"(addr));
}
__device__ __forceinline__ void mma16816(float* d, const uint32_t* a, uint32_t b0, uint32_t b1) {
    asm volatile(
        "mma.sync.aligned.m16n8k16.row.col.f32.bf16.bf16.f32 "
        "{%0,%1,%2,%3}, {%4,%5,%6,%7}, {%8,%9}, {%0,%1,%2,%3};"
        : "+f"(d[0]), "+f"(d[1]), "+f"(d[2]), "+f"(d[3])
        : "r"(a[0]), "r"(a[1]), "r"(a[2]), "r"(a[3]), "r"(b0), "r"(b1));
}
__device__ __forceinline__ float lrelu(float x) { return x > 0.f ? x : 0.2f * x; }

__device__ __forceinline__ void aek_reduce(const float* We, const float* ae, float* out, int t)
{
    float p = We[t] * ae[t];
#pragma unroll
    for (int off = 16; off > 0; off >>= 1)
        p += __shfl_down_sync(0xffffffffu, p, off);
    __shared__ float sh[8];
    int w = t >> 5, lane = t & 31;
    if (lane == 0) sh[w] = p;
    __syncthreads();
    if (t < HH) out[t] = sh[2 * t] + sh[2 * t + 1];
}

// ---------------- bucket CSR (side stream) -----------------------------------
__global__ void k_zero(const float* __restrict__ We1, const float* __restrict__ ae1,
                       const float* __restrict__ We2, const float* __restrict__ ae2)
{
    int i = blockIdx.x * blockDim.x + threadIdx.x;
    if (i < NN) g_cursor[i] = 0;
    if (blockIdx.x == 0) aek_reduce(We1, ae1, g_aek, threadIdx.x);
    if (blockIdx.x == 1) aek_reduce(We2, ae2, g_aek2, threadIdx.x);
}

__global__ void k_fill(const int* __restrict__ dst, const int* __restrict__ src,
                       const float* __restrict__ eattr, const float* __restrict__ eatten)
{
    int e = blockIdx.x * blockDim.x + threadIdx.x;
    if (e >= EE) return;
    int d = dst[e];
    int pos = atomicAdd(&g_cursor[d], 1);
    if (pos < BCAP)
        g_ebkt[(size_t)d * BCAP + pos] =
            make_int4(src[e], e, __float_as_int(eattr[e]), __float_as_int(eatten[e]));
}

// ---------------- bf16-split conversions (vectorized) ------------------------
__global__ void k_cvtA(const float* __restrict__ src)
{
    int i = blockIdx.x * blockDim.x + threadIdx.x;   // [0, NN*32)
    if (i >= NN * 32) return;
    int m = i >> 5, t = i & 31;
    float4 v = *(const float4*)&src[(size_t)m * 128 + t * 4];
    __nv_bfloat16 h0 = __float2bfloat16_rn(v.x), h1 = __float2bfloat16_rn(v.y);
    __nv_bfloat16 h2 = __float2bfloat16_rn(v.z), h3 = __float2bfloat16_rn(v.w);
    __nv_bfloat16 l0 = __float2bfloat16_rn(v.x - __bfloat162float(h0));
    __nv_bfloat16 l1 = __float2bfloat16_rn(v.y - __bfloat162float(h1));
    __nv_bfloat16 l2 = __float2bfloat16_rn(v.z - __bfloat162float(h2));
    __nv_bfloat16 l3 = __float2bfloat16_rn(v.w - __bfloat162float(h3));
    size_t base = (size_t)m * 256 + t * 4;
    __nv_bfloat162 ph0; ph0.x = h0; ph0.y = h1;
    __nv_bfloat162 ph1; ph1.x = h2; ph1.y = h3;
    __nv_bfloat162 pl0; pl0.x = l0; pl0.y = l1;
    __nv_bfloat162 pl1; pl1.x = l2; pl1.y = l3;
    *(__nv_bfloat162*)&g_A3[base] = ph0;
    *(__nv_bfloat162*)&g_A3[base + 2] = ph1;
    *(__nv_bfloat162*)&g_A3[base + 128] = pl0;
    *(__nv_bfloat162*)&g_A3[base + 130] = pl1;
}

__global__ void k_cvtW(const float* __restrict__ W, int K, __nv_bfloat16* __restrict__ B3)
{
    int i = blockIdx.x * blockDim.x + threadIdx.x;
    if (i >= K * 256) return;
    int k = i >> 8, n = i & 255;
    float v = W[i];
    __nv_bfloat16 h = __float2bfloat16_rn(v);
    __nv_bfloat16 l = __float2bfloat16_rn(v - __bfloat162float(h));
    B3[(size_t)k * 256 + n] = h;
    B3[(size_t)(K + k) * 256 + n] = l;
    B3[(size_t)(2 * K + k) * 256 + n] = h;
}

// ---------------- HMMA GEMM + fused alpha_src/dst (smem-reduced) ------------
#define ASTR 40
#define BSTR 136

__device__ __forceinline__ void gemm_load(uint32_t as_dst, uint32_t bs_dst,
                                          const __nv_bfloat16* __restrict__ A,
                                          const __nv_bfloat16* __restrict__ B,
                                          int row0, int n0, int kA, int kB,
                                          int Astride, int tid)
{
#pragma unroll
    for (int c = tid; c < 512; c += 256) {
        int r = c >> 2, off = c & 3;
        uint32_t d = as_dst + (uint32_t)(r * ASTR + off * 8) * 2;
        const void* s = A + (size_t)(row0 + r) * Astride + kA + off * 8;
        asm volatile("cp.async.cg.shared.global [%0], [%1], 16;" :: "r"(d), "l"(s));
    }
#pragma unroll
    for (int c = tid; c < 512; c += 256) {
        int r = c >> 4, off = c & 15;
        uint32_t d = bs_dst + (uint32_t)(r * BSTR + off * 8) * 2;
        const void* s = B + (size_t)(kB + r) * 256 + n0 + off * 8;
        asm volatile("cp.async.cg.shared.global [%0], [%1], 16;" :: "r"(d), "l"(s));
    }
    asm volatile("cp.async.commit_group;");
}

__global__ void __launch_bounds__(256, 2)
k_gemm_mma(const __nv_bfloat16* __restrict__ A, const __nv_bfloat16* __restrict__ B,
           __half* __restrict__ Ch, int Kbase, int tshift, int rowOff,
           const float* __restrict__ a_src, const float* __restrict__ a_dst,
           float* __restrict__ as_out, float* __restrict__ ad_out)
{
    __shared__ __align__(16) __nv_bfloat16 As[2][128 * ASTR];
    __shared__ __align__(16) __nv_bfloat16 Bs[2][32 * BSTR];
    __shared__ float sAS[128][2], sAD[128][2];
    int tid = threadIdx.x;
    int wid = tid >> 5, lane = tid & 31;
    int row0 = rowOff + blockIdx.y * 128;
    int n0 = blockIdx.x * 128;
    int wm = (wid >> 2) * 64;
    int wn = (wid & 3) * 32;
    int Astride = 2 * Kbase;
    int tpcm = (1 << tshift) - 1;

    if (tid < 128) { sAS[tid][0] = 0.f; sAS[tid][1] = 0.f;
                     sAD[tid][0] = 0.f; sAD[tid][1] = 0.f; }

    float acc[4][4][4];
#pragma unroll
    for (int i = 0; i < 4; i++)
#pragma unroll
        for (int j = 0; j < 4; j++)
#pragma unroll
            for (int q = 0; q < 4; q++) acc[i][j][q] = 0.f;

    uint32_t asb = smem_u32(As), bsb = smem_u32(Bs);
    const int NIT = 3 << tshift;

    gemm_load(asb, bsb, A, B, row0, n0, 0, 0, Astride, tid);

    for (int it = 0; it < NIT; it++) {
        int buf = it & 1;
        if (it + 1 < NIT) {
            int c = it + 1;
            int term = c >> tshift, kc = c & tpcm;
            int kA = ((term == 2) ? Kbase : 0) + kc * 32;
            gemm_load(asb + ((it + 1) & 1) * 128 * ASTR * 2,
                      bsb + ((it + 1) & 1) * 32 * BSTR * 2,
                      A, B, row0, n0, kA, c * 32, Astride, tid);
            asm volatile("cp.async.wait_group 1;");
        } else {
            asm volatile("cp.async.wait_group 0;");
        }
        __syncthreads();

        uint32_t abuf = asb + buf * 128 * ASTR * 2;
        uint32_t bbuf = bsb + buf * 32 * BSTR * 2;
#pragma unroll
        for (int ks = 0; ks < 32; ks += 16) {
            uint32_t af[4][4];
            int arow = wm + (lane & 7) + ((lane & 8) ? 8 : 0);
            int acol = ks + ((lane & 16) ? 8 : 0);
#pragma unroll
            for (int ms = 0; ms < 4; ms++) {
                uint32_t ad = abuf + (uint32_t)((arow + ms * 16) * ASTR + acol) * 2;
                ldsm_x4(ad, af[ms][0], af[ms][1], af[ms][2], af[ms][3]);
            }
            uint32_t bfr[2][4];
            int bk = ks + ((lane & 8) ? 8 : 0) + (lane & 7);
            int bnl = ((lane & 16) ? 8 : 0);
#pragma unroll
            for (int p = 0; p < 2; p++) {
                uint32_t bd = bbuf + (uint32_t)(bk * BSTR + wn + p * 16 + bnl) * 2;
                ldsm_x4t(bd, bfr[p][0], bfr[p][1], bfr[p][2], bfr[p][3]);
            }
#pragma unroll
            for (int ms = 0; ms < 4; ms++)
#pragma unroll
                for (int ns = 0; ns < 4; ns++) {
                    int p = ns >> 1, q = ns & 1;
                    mma16816(acc[ms][ns], af[ms], bfr[p][q * 2], bfr[p][q * 2 + 1]);
                }
        }
        __syncthreads();
    }

    int hloc = wn >> 6;
#pragma unroll
    for (int ms = 0; ms < 4; ms++) {
        int rl = wm + ms * 16 + (lane >> 2);
        int r0 = row0 + rl;
        float ps0 = 0.f, pd0 = 0.f, ps8 = 0.f, pd8 = 0.f;
#pragma unroll
        for (int ns = 0; ns < 4; ns++) {
            int cc = n0 + wn + ns * 8 + (lane & 3) * 2;
            float s0 = a_src[cc], s1 = a_src[cc + 1];
            float d0 = a_dst[cc], d1 = a_dst[cc + 1];
            ps0 += acc[ms][ns][0] * s0 + acc[ms][ns][1] * s1;
            pd0 += acc[ms][ns][0] * d0 + acc[ms][ns][1] * d1;
            ps8 += acc[ms][ns][2] * s0 + acc[ms][ns][3] * s1;
            pd8 += acc[ms][ns][2] * d0 + acc[ms][ns][3] * d1;
            if (r0 < NN)
                *(__half2*)&Ch[(size_t)r0 * 256 + cc] =
                    __floats2half2_rn(acc[ms][ns][0], acc[ms][ns][1]);
            if (r0 + 8 < NN)
                *(__half2*)&Ch[(size_t)(r0 + 8) * 256 + cc] =
                    __floats2half2_rn(acc[ms][ns][2], acc[ms][ns][3]);
        }
        ps0 += __shfl_down_sync(0xffffffffu, ps0, 2, 4);
        ps0 += __shfl_down_sync(0xffffffffu, ps0, 1, 4);
        pd0 += __shfl_down_sync(0xffffffffu, pd0, 2, 4);
        pd0 += __shfl_down_sync(0xffffffffu, pd0, 1, 4);
        ps8 += __shfl_down_sync(0xffffffffu, ps8, 2, 4);
        ps8 += __shfl_down_sync(0xffffffffu, ps8, 1, 4);
        pd8 += __shfl_down_sync(0xffffffffu, pd8, 2, 4);
        pd8 += __shfl_down_sync(0xffffffffu, pd8, 1, 4);
        if ((lane & 3) == 0) {
            atomicAdd(&sAS[rl][hloc], ps0);
            atomicAdd(&sAD[rl][hloc], pd0);
            atomicAdd(&sAS[rl + 8][hloc], ps8);
            atomicAdd(&sAD[rl + 8][hloc], pd8);
        }
    }
    __syncthreads();
    {
        int rl = tid >> 1, j = tid & 1;
        int r = row0 + rl;
        if (r < NN) {
            int hbase = n0 >> 6;
            as_out[r * 4 + hbase + j] = sAS[rl][j];
            ad_out[r * 4 + hbase + j] = sAD[rl][j];
        }
    }
}

// ---------------- fused softmax + aggregation (block per node, 1 edge/thread)
__global__ void __launch_bounds__(128)
k_fagg(const __half* __restrict__ xhh, const float* __restrict__ bias,
       const float* __restrict__ aek, const float* __restrict__ as_buf,
       const float* __restrict__ ad_buf, float* __restrict__ w_out,
       float* __restrict__ out_f32, int mode, int nodeOff)
{
    __shared__ int   s_src[BCAP];
    __shared__ float s_co[BCAP * 4];
    __shared__ float s_red[4][4];   // [warp][head]
    int n = nodeOff + blockIdx.x;
    int t = threadIdx.x;
    int warp = t >> 5, lane = t & 31;
    int h = t >> 5;
    size_t lo = (size_t)n * BCAP;
    int cnt = min(g_cursor[n], BCAP);
    bool ok = (t < cnt);

    // ---- phase 1: alpha + block softmax (1 edge per thread) ----
    float4 ad4 = *(const float4*)&ad_buf[n * 4];
    float4 ak = *(const float4*)aek;
    float4 a = make_float4(-INFINITY, -INFINITY, -INFINITY, -INFINITY);
    int eo = 0; float at = 0.f;
    if (ok) {
        int4 p = g_ebkt[lo + t];
        float ea = __int_as_float(p.z);
        float4 as4 = *(const float4*)&as_buf[p.x * 4];
        a.x = lrelu(as4.x + ad4.x + ak.x * ea);
        a.y = lrelu(as4.y + ad4.y + ak.y * ea);
        a.z = lrelu(as4.z + ad4.z + ak.z * ea);
        a.w = lrelu(as4.w + ad4.w + ak.w * ea);
        eo = p.y; at = __int_as_float(p.w);
        s_src[t] = p.x;
    }
    // block max per head
    float4 m = a;
#pragma unroll
    for (int off = 16; off > 0; off >>= 1) {
        m.x = fmaxf(m.x, __shfl_xor_sync(0xffffffffu, m.x, off));
        m.y = fmaxf(m.y, __shfl_xor_sync(0xffffffffu, m.y, off));
        m.z = fmaxf(m.z, __shfl_xor_sync(0xffffffffu, m.z, off));
        m.w = fmaxf(m.w, __shfl_xor_sync(0xffffffffu, m.w, off));
    }
    if (lane == 0) *(float4*)&s_red[warp][0] = m;
    __syncthreads();
    {
        float4 r0 = *(float4*)&s_red[0][0];
        float4 r1 = *(float4*)&s_red[1][0];
        float4 r2 = *(float4*)&s_red[2][0];
        float4 r3 = *(float4*)&s_red[3][0];
        m.x = fmaxf(fmaxf(r0.x, r1.x), fmaxf(r2.x, r3.x));
        m.y = fmaxf(fmaxf(r0.y, r1.y), fmaxf(r2.y, r3.y));
        m.z = fmaxf(fmaxf(r0.z, r1.z), fmaxf(r2.z, r3.z));
        m.w = fmaxf(fmaxf(r0.w, r1.w), fmaxf(r2.w, r3.w));
    }
    __syncthreads();   // s_red reuse below
    // exp + block sum
    float4 ex = make_float4(0.f, 0.f, 0.f, 0.f);
    if (ok) {
        ex.x = expf(a.x - m.x); ex.y = expf(a.y - m.y);
        ex.z = expf(a.z - m.z); ex.w = expf(a.w - m.w);
    }
    float4 sm = ex;
#pragma unroll
    for (int off = 16; off > 0; off >>= 1) {
        sm.x += __shfl_xor_sync(0xffffffffu, sm.x, off);
        sm.y += __shfl_xor_sync(0xffffffffu, sm.y, off);
        sm.z += __shfl_xor_sync(0xffffffffu, sm.z, off);
        sm.w += __shfl_xor_sync(0xffffffffu, sm.w, off);
    }
    if (lane == 0) *(float4*)&s_red[warp][0] = sm;
    __syncthreads();
    {
        float4 r0 = *(float4*)&s_red[0][0];
        float4 r1 = *(float4*)&s_red[1][0];
        float4 r2 = *(float4*)&s_red[2][0];
        float4 r3 = *(float4*)&s_red[3][0];
        sm.x = r0.x + r1.x + r2.x + r3.x;
        sm.y = r0.y + r1.y + r2.y + r3.y;
        sm.z = r0.z + r1.z + r2.z + r3.z;
        sm.w = r0.w + r1.w + r2.w + r3.w;
    }
    if (ok) {
        float4 w;
        w.x = ex.x / (sm.x + 1e-16f); w.y = ex.y / (sm.y + 1e-16f);
        w.z = ex.z / (sm.z + 1e-16f); w.w = ex.w / (sm.w + 1e-16f);
        *(float4*)&w_out[(size_t)eo * 4] = w;
        *(float4*)&s_co[t * 4] = make_float4(w.x * at, w.y * at, w.z * at, w.w * at);
    }
    __syncthreads();

    // ---- phase 2: aggregation (channels 2t, 2t+1) ----
    float acc0 = 0.f, acc1 = 0.f;
    int i = 0;
    for (; i + 3 < cnt; i += 4) {
        __half2 u0 = *(const __half2*)&xhh[(size_t)s_src[i] * 256 + 2 * t];
        __half2 u1 = *(const __half2*)&xhh[(size_t)s_src[i + 1] * 256 + 2 * t];
        __half2 u2 = *(const __half2*)&xhh[(size_t)s_src[i + 2] * 256 + 2 * t];
        __half2 u3 = *(const __half2*)&xhh[(size_t)s_src[i + 3] * 256 + 2 * t];
        float c0 = s_co[i * 4 + h], c1 = s_co[(i + 1) * 4 + h];
        float c2 = s_co[(i + 2) * 4 + h], c3 = s_co[(i + 3) * 4 + h];
        float2 f0 = __half22float2(u0), f1 = __half22float2(u1);
        float2 f2 = __half22float2(u2), f3 = __half22float2(u3);
        acc0 += f0.x * c0 + f1.x * c1 + f2.x * c2 + f3.x * c3;
        acc1 += f0.y * c0 + f1.y * c1 + f2.y * c2 + f3.y * c3;
    }
    for (; i < cnt; i++) {
        __half2 u = *(const __half2*)&xhh[(size_t)s_src[i] * 256 + 2 * t];
        float c = s_co[i * 4 + h];
        float2 f = __half22float2(u);
        acc0 += f.x * c;
        acc1 += f.y * c;
    }

    float v0 = acc0 + bias[2 * t];
    float v1 = acc1 + bias[2 * t + 1];
    if (mode) {
        __nv_bfloat16 h0 = __float2bfloat16_rn(v0);
        __nv_bfloat16 h1b = __float2bfloat16_rn(v1);
        __nv_bfloat16 l0 = __float2bfloat16_rn(v0 - __bfloat162float(h0));
        __nv_bfloat16 l1 = __float2bfloat16_rn(v1 - __bfloat162float(h1b));
        __nv_bfloat162 ph; ph.x = h0; ph.y = h1b;
        __nv_bfloat162 pl; pl.x = l0; pl.y = l1;
        size_t base = (size_t)n * 512;
        ((__nv_bfloat162*)(g_A3 + base))[t] = ph;
        ((__nv_bfloat162*)(g_A3 + base + 256))[t] = pl;
    } else {
        out_f32[(size_t)n * 256 + 2 * t]     = v0;
        out_f32[(size_t)n * 256 + 2 * t + 1] = v1;
    }
}

// ---------------- driver ----------------------------------------------------
extern "C" void kernel_launch(void* const* d_in, const int* in_sizes, int n_in,
                              void* d_out, int out_size)
{
    const float* x      = (const float*)d_in[0];
    const int*   ei     = (const int*)d_in[1];
    const float* eattr  = (const float*)d_in[3];
    const float* eatten = (const float*)d_in[4];
    const float* W1     = (const float*)d_in[5];
    const float* as1    = (const float*)d_in[6];
    const float* ad1    = (const float*)d_in[7];
    const float* We1    = (const float*)d_in[8];
    const float* ae1    = (const float*)d_in[9];
    const float* b1     = (const float*)d_in[10];
    const float* W2     = (const float*)d_in[11];
    const float* as2    = (const float*)d_in[12];
    const float* ad2    = (const float*)d_in[13];
    const float* We2    = (const float*)d_in[14];
    const float* ae2    = (const float*)d_in[15];
    const float* b2     = (const float*)d_in[16];

    const int* src = ei;
    const int* dst = ei + EE;

    float* out    = (float*)d_out;
    float* h_out  = out;
    float* w1_out = out + (size_t)NN * FDIM;
    float* w2_out = w1_out + (size_t)EE * HH;

    __half* xhh = nullptr; __half* xhh2 = nullptr;
    __nv_bfloat16* A3 = nullptr; __nv_bfloat16* B3 = nullptr; __nv_bfloat16* B3b = nullptr;
    float* aekp = nullptr; float* aek2p = nullptr;
    float* asP = nullptr; float* adP = nullptr; float* as2P = nullptr; float* ad2P = nullptr;
    cudaGetSymbolAddress((void**)&xhh, g_xhh);
    cudaGetSymbolAddress((void**)&xhh2, g_xhh2);
    cudaGetSymbolAddress((void**)&A3, g_A3);
    cudaGetSymbolAddress((void**)&B3, g_B3);
    cudaGetSymbolAddress((void**)&B3b, g_B3b);
    cudaGetSymbolAddress((void**)&aekp, g_aek);
    cudaGetSymbolAddress((void**)&aek2p, g_aek2);
    cudaGetSymbolAddress((void**)&asP, g_as);
    cudaGetSymbolAddress((void**)&adP, g_ad);
    cudaGetSymbolAddress((void**)&as2P, g_as2);
    cudaGetSymbolAddress((void**)&ad2P, g_ad2);

    static cudaStream_t s1;
    static cudaEvent_t evRoot, evCsr, evA, evG2a, evG2b, evEnd;
    static bool inited = false;
    if (!inited) {
        cudaStreamCreateWithFlags(&s1, cudaStreamNonBlocking);
        cudaEventCreateWithFlags(&evRoot, cudaEventDisableTiming);
        cudaEventCreateWithFlags(&evCsr,  cudaEventDisableTiming);
        cudaEventCreateWithFlags(&evA,    cudaEventDisableTiming);
        cudaEventCreateWithFlags(&evG2a,  cudaEventDisableTiming);
        cudaEventCreateWithFlags(&evG2b,  cudaEventDisableTiming);
        cudaEventCreateWithFlags(&evEnd,  cudaEventDisableTiming);
        inited = true;
    }

    const int EB = (EE + 255) / 256;

    // fork root
    cudaEventRecord(evRoot, 0);
    cudaStreamWaitEvent(s1, evRoot, 0);

    // s1: bucket CSR, then W2 conversion
    k_zero<<<(NN + 255) / 256, 256, 0, s1>>>(We1, ae1, We2, ae2);
    k_fill<<<EB, 256, 0, s1>>>(dst, src, eattr, eatten);
    cudaEventRecord(evCsr, s1);
    k_cvtW<<<(256 * 256 + 255) / 256, 256, 0, s1>>>(W2, 256, B3b);

    // main: layer-1 transform
    k_cvtA<<<(NN * 32 + 255) / 256, 256>>>(x);
    k_cvtW<<<(128 * 256 + 255) / 256, 256>>>(W1, 128, B3);
    k_gemm_mma<<<dim3(2, 157), 256>>>(A3, B3, xhh, 128, 2, 0, as1, ad1, asP, adP);

    // layer-1 fused edge phase (needs CSR + gemm1)
    cudaStreamWaitEvent(0, evCsr, 0);
    k_fagg<<<NHALF_ROWS, 128>>>(xhh, b1, aekp, asP, adP, w1_out, nullptr, 1, 0);
    cudaEventRecord(evA, 0);
    cudaStreamWaitEvent(s1, evA, 0);
    k_gemm_mma<<<dim3(2, 79), 256, 0, s1>>>(A3, B3b, xhh2, 256, 3, 0, as2, ad2, as2P, ad2P);
    cudaEventRecord(evG2a, s1);

    k_fagg<<<NN - NHALF_ROWS, 128>>>(xhh, b1, aekp, asP, adP, w1_out, nullptr, 1, NHALF_ROWS);
    k_gemm_mma<<<dim3(2, 78), 256>>>(A3, B3b, xhh2, 256, 3, NHALF_ROWS, as2, ad2, as2P, ad2P);
    cudaEventRecord(evG2b, 0);

    // layer-2 fused tail: halves split across streams
    cudaStreamWaitEvent(s1, evG2b, 0);
    k_fagg<<<10000, 128, 0, s1>>>(xhh2, b2, aek2p, as2P, ad2P, w2_out, h_out, 0, 10000);
    cudaEventRecord(evEnd, s1);

    cudaStreamWaitEvent(0, evG2a, 0);
    k_fagg<<<10000, 128>>>(xhh2, b2, aek2p, as2P, ad2P, w2_out, h_out, 0, 0);
    cudaStreamWaitEvent(0, evEnd, 0);
}

// round 17
// speedup vs baseline: 1.0533x; 1.0533x over previous
#include <cuda_runtime.h>
#include <cuda_bf16.h>
#include <cuda_fp16.h>
#include <math.h>
#include <stdint.h>

#define NN 20000
#define NNPAD 20096          // 157 * 128
#define EE 640000
#define HH 4
#define FDIM 256
#define BCAP 128             // edge bucket capacity per node
#define NHALF_ROWS 10112     // 79 * 128 (gemm row-block aligned split)

// ---------------- scratch ----------------------------------------------------
__device__ __half g_xhh[NN * FDIM];    // layer-1 fp16 features
__device__ __half g_xhh2[NN * FDIM];   // layer-2 fp16 features
__device__ float g_as[NN * HH];
__device__ float g_ad[NN * HH];
__device__ float g_coeff[(size_t)NN * BCAP * HH];  // bucket-indexed
__device__ float g_aek[HH];
__device__ float g_aek2[HH];
__device__ int    g_cursor[NN];
__device__ int4   g_ebkt[(size_t)NN * BCAP];       // {src, eorig, eattr, eatten}
__device__ __nv_bfloat16 g_A3[(size_t)NNPAD * 512];  // [Ah|Al] row stride 2K
__device__ __nv_bfloat16 g_B3[768 * 256];
__device__ __nv_bfloat16 g_B3b[768 * 256];

// ---------------- helpers ----------------------------------------------------
__device__ __forceinline__ uint32_t smem_u32(const void* p) {
    uint32_t a;
    asm("{ .reg .u64 t; cvta.to.shared.u64 t, %1; cvt.u32.u64 %0, t; }" : "=r"(a) : "l"(p));
    return a;
}
__device__ __forceinline__ void ldsm_x4(uint32_t addr, uint32_t& r0, uint32_t& r1,
                                        uint32_t& r2, uint32_t& r3) {
    asm volatile("ldmatrix.sync.aligned.m8n8.x4.shared.b16 {%0,%1,%2,%3}, [%4];"
                 : "=r"(r0), "=r"(r1), "=r"(r2), "=r"(r3) : "r"(addr));
}
__device__ __forceinline__ void ldsm_x4t(uint32_t addr, uint32_t& r0, uint32_t& r1,
                                         uint32_t& r2, uint32_t& r3) {
    asm volatile("ldmatrix.sync.aligned.m8n8.x4.trans.shared.b16 {%0,%1,%2,%3}, [%4];"
                 : "=r"(r0), "=r"(r1), "=r"(r2), "=r"(r3) : "r"(addr));
}
__device__ __forceinline__ void mma16816(float* d, const uint32_t* a, uint32_t b0, uint32_t b1) {
    asm volatile(
        "mma.sync.aligned.m16n8k16.row.col.f32.bf16.bf16.f32 "
        "{%0,%1,%2,%3}, {%4,%5,%6,%7}, {%8,%9}, {%0,%1,%2,%3};"
        : "+f"(d[0]), "+f"(d[1]), "+f"(d[2]), "+f"(d[3])
        : "r"(a[0]), "r"(a[1]), "r"(a[2]), "r"(a[3]), "r"(b0), "r"(b1));
}
__device__ __forceinline__ float lrelu(float x) { return x > 0.f ? x : 0.2f * x; }

__device__ __forceinline__ void aek_reduce(const float* We, const float* ae, float* out, int t)
{
    float p = We[t] * ae[t];
#pragma unroll
    for (int off = 16; off > 0; off >>= 1)
        p += __shfl_down_sync(0xffffffffu, p, off);
    __shared__ float sh[8];
    int w = t >> 5, lane = t & 31;
    if (lane == 0) sh[w] = p;
    __syncthreads();
    if (t < HH) out[t] = sh[2 * t] + sh[2 * t + 1];
}

// ---------------- bucket CSR (side stream) -----------------------------------
__global__ void k_zero(const float* __restrict__ We1, const float* __restrict__ ae1,
                       const float* __restrict__ We2, const float* __restrict__ ae2)
{
    int i = blockIdx.x * blockDim.x + threadIdx.x;
    if (i < NN) g_cursor[i] = 0;
    if (blockIdx.x == 0) aek_reduce(We1, ae1, g_aek, threadIdx.x);
    if (blockIdx.x == 1) aek_reduce(We2, ae2, g_aek2, threadIdx.x);
}

__global__ void k_fill(const int* __restrict__ dst, const int* __restrict__ src,
                       const float* __restrict__ eattr, const float* __restrict__ eatten)
{
    int e = blockIdx.x * blockDim.x + threadIdx.x;
    if (e >= EE) return;
    int d = dst[e];
    int pos = atomicAdd(&g_cursor[d], 1);
    if (pos < BCAP)
        g_ebkt[(size_t)d * BCAP + pos] =
            make_int4(src[e], e, __float_as_int(eattr[e]), __float_as_int(eatten[e]));
}

// ---------------- fused layer-1 conversions: A (vectorized) + W1 -------------
// blocks [0, 2500): A rows; blocks [2500, 2628): W1
__global__ void k_cvt1(const float* __restrict__ x, const float* __restrict__ W1)
{
    int b = blockIdx.x;
    if (b < 2500) {
        int i = b * 256 + threadIdx.x;     // [0, NN*32)
        if (i >= NN * 32) return;
        int m = i >> 5, t = i & 31;
        float4 v = *(const float4*)&x[(size_t)m * 128 + t * 4];
        __nv_bfloat16 h0 = __float2bfloat16_rn(v.x), h1 = __float2bfloat16_rn(v.y);
        __nv_bfloat16 h2 = __float2bfloat16_rn(v.z), h3 = __float2bfloat16_rn(v.w);
        __nv_bfloat16 l0 = __float2bfloat16_rn(v.x - __bfloat162float(h0));
        __nv_bfloat16 l1 = __float2bfloat16_rn(v.y - __bfloat162float(h1));
        __nv_bfloat16 l2 = __float2bfloat16_rn(v.z - __bfloat162float(h2));
        __nv_bfloat16 l3 = __float2bfloat16_rn(v.w - __bfloat162float(h3));
        size_t base = (size_t)m * 256 + t * 4;
        __nv_bfloat162 ph0; ph0.x = h0; ph0.y = h1;
        __nv_bfloat162 ph1; ph1.x = h2; ph1.y = h3;
        __nv_bfloat162 pl0; pl0.x = l0; pl0.y = l1;
        __nv_bfloat162 pl1; pl1.x = l2; pl1.y = l3;
        *(__nv_bfloat162*)&g_A3[base] = ph0;
        *(__nv_bfloat162*)&g_A3[base + 2] = ph1;
        *(__nv_bfloat162*)&g_A3[base + 128] = pl0;
        *(__nv_bfloat162*)&g_A3[base + 130] = pl1;
    } else {
        int i = (b - 2500) * 256 + threadIdx.x;   // [0, 128*256)
        if (i >= 128 * 256) return;
        int k = i >> 8, n = i & 255;
        float v = W1[i];
        __nv_bfloat16 h = __float2bfloat16_rn(v);
        __nv_bfloat16 l = __float2bfloat16_rn(v - __bfloat162float(h));
        g_B3[(size_t)k * 256 + n] = h;
        g_B3[(size_t)(128 + k) * 256 + n] = l;
        g_B3[(size_t)(256 + k) * 256 + n] = h;
    }
}

__global__ void k_cvtW(const float* __restrict__ W, int K, __nv_bfloat16* __restrict__ B3)
{
    int i = blockIdx.x * blockDim.x + threadIdx.x;
    if (i >= K * 256) return;
    int k = i >> 8, n = i & 255;
    float v = W[i];
    __nv_bfloat16 h = __float2bfloat16_rn(v);
    __nv_bfloat16 l = __float2bfloat16_rn(v - __bfloat162float(h));
    B3[(size_t)k * 256 + n] = h;
    B3[(size_t)(K + k) * 256 + n] = l;
    B3[(size_t)(2 * K + k) * 256 + n] = h;
}

// ---------------- HMMA GEMM + fused alpha_src/dst (smem-reduced) ------------
#define ASTR 40
#define BSTR 136

__device__ __forceinline__ void gemm_load(uint32_t as_dst, uint32_t bs_dst,
                                          const __nv_bfloat16* __restrict__ A,
                                          const __nv_bfloat16* __restrict__ B,
                                          int row0, int n0, int kA, int kB,
                                          int Astride, int tid)
{
#pragma unroll
    for (int c = tid; c < 512; c += 256) {
        int r = c >> 2, off = c & 3;
        uint32_t d = as_dst + (uint32_t)(r * ASTR + off * 8) * 2;
        const void* s = A + (size_t)(row0 + r) * Astride + kA + off * 8;
        asm volatile("cp.async.cg.shared.global [%0], [%1], 16;" :: "r"(d), "l"(s));
    }
#pragma unroll
    for (int c = tid; c < 512; c += 256) {
        int r = c >> 4, off = c & 15;
        uint32_t d = bs_dst + (uint32_t)(r * BSTR + off * 8) * 2;
        const void* s = B + (size_t)(kB + r) * 256 + n0 + off * 8;
        asm volatile("cp.async.cg.shared.global [%0], [%1], 16;" :: "r"(d), "l"(s));
    }
    asm volatile("cp.async.commit_group;");
}

__global__ void __launch_bounds__(256, 2)
k_gemm_mma(const __nv_bfloat16* __restrict__ A, const __nv_bfloat16* __restrict__ B,
           __half* __restrict__ Ch, int Kbase, int tshift, int rowOff,
           const float* __restrict__ a_src, const float* __restrict__ a_dst)
{
    __shared__ __align__(16) __nv_bfloat16 As[2][128 * ASTR];
    __shared__ __align__(16) __nv_bfloat16 Bs[2][32 * BSTR];
    __shared__ float sAS[128][2], sAD[128][2];
    int tid = threadIdx.x;
    int wid = tid >> 5, lane = tid & 31;
    int row0 = rowOff + blockIdx.y * 128;
    int n0 = blockIdx.x * 128;
    int wm = (wid >> 2) * 64;
    int wn = (wid & 3) * 32;
    int Astride = 2 * Kbase;
    int tpcm = (1 << tshift) - 1;

    if (tid < 128) { sAS[tid][0] = 0.f; sAS[tid][1] = 0.f;
                     sAD[tid][0] = 0.f; sAD[tid][1] = 0.f; }

    float acc[4][4][4];
#pragma unroll
    for (int i = 0; i < 4; i++)
#pragma unroll
        for (int j = 0; j < 4; j++)
#pragma unroll
            for (int q = 0; q < 4; q++) acc[i][j][q] = 0.f;

    uint32_t asb = smem_u32(As), bsb = smem_u32(Bs);
    const int NIT = 3 << tshift;

    gemm_load(asb, bsb, A, B, row0, n0, 0, 0, Astride, tid);

    for (int it = 0; it < NIT; it++) {
        int buf = it & 1;
        if (it + 1 < NIT) {
            int c = it + 1;
            int term = c >> tshift, kc = c & tpcm;
            int kA = ((term == 2) ? Kbase : 0) + kc * 32;
            gemm_load(asb + ((it + 1) & 1) * 128 * ASTR * 2,
                      bsb + ((it + 1) & 1) * 32 * BSTR * 2,
                      A, B, row0, n0, kA, c * 32, Astride, tid);
            asm volatile("cp.async.wait_group 1;");
        } else {
            asm volatile("cp.async.wait_group 0;");
        }
        __syncthreads();

        uint32_t abuf = asb + buf * 128 * ASTR * 2;
        uint32_t bbuf = bsb + buf * 32 * BSTR * 2;
#pragma unroll
        for (int ks = 0; ks < 32; ks += 16) {
            uint32_t af[4][4];
            int arow = wm + (lane & 7) + ((lane & 8) ? 8 : 0);
            int acol = ks + ((lane & 16) ? 8 : 0);
#pragma unroll
            for (int ms = 0; ms < 4; ms++) {
                uint32_t ad = abuf + (uint32_t)((arow + ms * 16) * ASTR + acol) * 2;
                ldsm_x4(ad, af[ms][0], af[ms][1], af[ms][2], af[ms][3]);
            }
            uint32_t bfr[2][4];
            int bk = ks + ((lane & 8) ? 8 : 0) + (lane & 7);
            int bnl = ((lane & 16) ? 8 : 0);
#pragma unroll
            for (int p = 0; p < 2; p++) {
                uint32_t bd = bbuf + (uint32_t)(bk * BSTR + wn + p * 16 + bnl) * 2;
                ldsm_x4t(bd, bfr[p][0], bfr[p][1], bfr[p][2], bfr[p][3]);
            }
#pragma unroll
            for (int ms = 0; ms < 4; ms++)
#pragma unroll
                for (int ns = 0; ns < 4; ns++) {
                    int p = ns >> 1, q = ns & 1;
                    mma16816(acc[ms][ns], af[ms], bfr[p][q * 2], bfr[p][q * 2 + 1]);
                }
        }
        __syncthreads();
    }

    // hoisted a_src/a_dst values for this thread's 8 columns
    float sv[4][2], dv[4][2];
#pragma unroll
    for (int ns = 0; ns < 4; ns++) {
        int cc = n0 + wn + ns * 8 + (lane & 3) * 2;
        sv[ns][0] = a_src[cc]; sv[ns][1] = a_src[cc + 1];
        dv[ns][0] = a_dst[cc]; dv[ns][1] = a_dst[cc + 1];
    }

    int hloc = wn >> 6;
#pragma unroll
    for (int ms = 0; ms < 4; ms++) {
        int rl = wm + ms * 16 + (lane >> 2);
        int r0 = row0 + rl;
        float ps0 = 0.f, pd0 = 0.f, ps8 = 0.f, pd8 = 0.f;
#pragma unroll
        for (int ns = 0; ns < 4; ns++) {
            int cc = n0 + wn + ns * 8 + (lane & 3) * 2;
            ps0 += acc[ms][ns][0] * sv[ns][0] + acc[ms][ns][1] * sv[ns][1];
            pd0 += acc[ms][ns][0] * dv[ns][0] + acc[ms][ns][1] * dv[ns][1];
            ps8 += acc[ms][ns][2] * sv[ns][0] + acc[ms][ns][3] * sv[ns][1];
            pd8 += acc[ms][ns][2] * dv[ns][0] + acc[ms][ns][3] * dv[ns][1];
            if (r0 < NN)
                *(__half2*)&Ch[(size_t)r0 * 256 + cc] =
                    __floats2half2_rn(acc[ms][ns][0], acc[ms][ns][1]);
            if (r0 + 8 < NN)
                *(__half2*)&Ch[(size_t)(r0 + 8) * 256 + cc] =
                    __floats2half2_rn(acc[ms][ns][2], acc[ms][ns][3]);
        }
        ps0 += __shfl_down_sync(0xffffffffu, ps0, 2, 4);
        ps0 += __shfl_down_sync(0xffffffffu, ps0, 1, 4);
        pd0 += __shfl_down_sync(0xffffffffu, pd0, 2, 4);
        pd0 += __shfl_down_sync(0xffffffffu, pd0, 1, 4);
        ps8 += __shfl_down_sync(0xffffffffu, ps8, 2, 4);
        ps8 += __shfl_down_sync(0xffffffffu, ps8, 1, 4);
        pd8 += __shfl_down_sync(0xffffffffu, pd8, 2, 4);
        pd8 += __shfl_down_sync(0xffffffffu, pd8, 1, 4);
        if ((lane & 3) == 0) {
            atomicAdd(&sAS[rl][hloc], ps0);
            atomicAdd(&sAD[rl][hloc], pd0);
            atomicAdd(&sAS[rl + 8][hloc], ps8);
            atomicAdd(&sAD[rl + 8][hloc], pd8);
        }
    }
    __syncthreads();
    {
        int rl = tid >> 1, j = tid & 1;
        int r = row0 + rl;
        if (r < NN) {
            int hbase = n0 >> 6;
            g_as[r * 4 + hbase + j] = sAS[rl][j];
            g_ad[r * 4 + hbase + j] = sAD[rl][j];
        }
    }
}

// ---------------- fused alpha + softmax + norm (warp per node) ---------------
__global__ void __launch_bounds__(128)
k_fsm(float* __restrict__ w_out, const float* __restrict__ aek, int nodeOff)
{
    int warp = threadIdx.x >> 5, lane = threadIdx.x & 31;
    int n = nodeOff + blockIdx.x * 4 + warp;
    if (n >= NN) return;
    size_t lo = (size_t)n * BCAP;
    int cnt = min(g_cursor[n], BCAP);
    float4 ad4 = *(const float4*)&g_ad[n * 4];
    float4 ak = *(const float4*)aek;

    float4 aR[4]; float atR[4]; int eoR[4]; int okR[4];
    float4 m = make_float4(-INFINITY, -INFINITY, -INFINITY, -INFINITY);
#pragma unroll
    for (int j = 0; j < 4; j++) {
        int i = lane + 32 * j;
        okR[j] = (i < cnt);
        if (okR[j]) {
            int4 p = g_ebkt[lo + i];
            float ea = __int_as_float(p.z);
            float4 as4 = *(const float4*)&g_as[p.x * 4];
            float4 a;
            a.x = lrelu(as4.x + ad4.x + ak.x * ea);
            a.y = lrelu(as4.y + ad4.y + ak.y * ea);
            a.z = lrelu(as4.z + ad4.z + ak.z * ea);
            a.w = lrelu(as4.w + ad4.w + ak.w * ea);
            aR[j] = a; eoR[j] = p.y; atR[j] = __int_as_float(p.w);
            m.x = fmaxf(m.x, a.x); m.y = fmaxf(m.y, a.y);
            m.z = fmaxf(m.z, a.z); m.w = fmaxf(m.w, a.w);
        }
    }
#pragma unroll
    for (int off = 16; off > 0; off >>= 1) {
        m.x = fmaxf(m.x, __shfl_xor_sync(0xffffffffu, m.x, off));
        m.y = fmaxf(m.y, __shfl_xor_sync(0xffffffffu, m.y, off));
        m.z = fmaxf(m.z, __shfl_xor_sync(0xffffffffu, m.z, off));
        m.w = fmaxf(m.w, __shfl_xor_sync(0xffffffffu, m.w, off));
    }

    float4 sm = make_float4(0.f, 0.f, 0.f, 0.f);
    float4 exR[4];
#pragma unroll
    for (int j = 0; j < 4; j++) {
        if (okR[j]) {
            exR[j].x = expf(aR[j].x - m.x); exR[j].y = expf(aR[j].y - m.y);
            exR[j].z = expf(aR[j].z - m.z); exR[j].w = expf(aR[j].w - m.w);
            sm.x += exR[j].x; sm.y += exR[j].y; sm.z += exR[j].z; sm.w += exR[j].w;
        }
    }
#pragma unroll
    for (int off = 16; off > 0; off >>= 1) {
        sm.x += __shfl_xor_sync(0xffffffffu, sm.x, off);
        sm.y += __shfl_xor_sync(0xffffffffu, sm.y, off);
        sm.z += __shfl_xor_sync(0xffffffffu, sm.z, off);
        sm.w += __shfl_xor_sync(0xffffffffu, sm.w, off);
    }
    float4 rd;
    rd.x = 1.f / (sm.x + 1e-16f); rd.y = 1.f / (sm.y + 1e-16f);
    rd.z = 1.f / (sm.z + 1e-16f); rd.w = 1.f / (sm.w + 1e-16f);

#pragma unroll
    for (int j = 0; j < 4; j++) {
        if (okR[j]) {
            float4 w;
            w.x = exR[j].x * rd.x; w.y = exR[j].y * rd.y;
            w.z = exR[j].z * rd.z; w.w = exR[j].w * rd.w;
            *(float4*)&w_out[(size_t)eoR[j] * 4] = w;
            float at = atR[j];
            *(float4*)&g_coeff[(lo + lane + 32 * j) * 4] =
                make_float4(w.x * at, w.y * at, w.z * at, w.w * at);
        }
    }
}

// ---------------- aggregation: fp16 gather (block per node) ------------------
__global__ void __launch_bounds__(128)
k_agg16(const __half* __restrict__ xhh, const float* __restrict__ bias,
        float* __restrict__ out_f32, int mode, int nodeOff)
{
    __shared__ int   s_src[BCAP];
    __shared__ float s_co[BCAP * 4];
    int n = nodeOff + blockIdx.x;
    int t = threadIdx.x;
    int h = t >> 5;
    size_t lo = (size_t)n * BCAP;
    int cnt = min(g_cursor[n], BCAP);
    float acc0 = 0.f, acc1 = 0.f;

    if (t < cnt) {
        s_src[t] = g_ebkt[lo + t].x;
        ((float4*)s_co)[t] = *(const float4*)&g_coeff[(lo + t) * 4];
    }
    __syncthreads();
    int i = 0;
    for (; i + 3 < cnt; i += 4) {
        __half2 u0 = *(const __half2*)&xhh[(size_t)s_src[i] * 256 + 2 * t];
        __half2 u1 = *(const __half2*)&xhh[(size_t)s_src[i + 1] * 256 + 2 * t];
        __half2 u2 = *(const __half2*)&xhh[(size_t)s_src[i + 2] * 256 + 2 * t];
        __half2 u3 = *(const __half2*)&xhh[(size_t)s_src[i + 3] * 256 + 2 * t];
        float c0 = s_co[i * 4 + h], c1 = s_co[(i + 1) * 4 + h];
        float c2 = s_co[(i + 2) * 4 + h], c3 = s_co[(i + 3) * 4 + h];
        float2 f0 = __half22float2(u0), f1 = __half22float2(u1);
        float2 f2 = __half22float2(u2), f3 = __half22float2(u3);
        acc0 += f0.x * c0 + f1.x * c1 + f2.x * c2 + f3.x * c3;
        acc1 += f0.y * c0 + f1.y * c1 + f2.y * c2 + f3.y * c3;
    }
    for (; i < cnt; i++) {
        __half2 u = *(const __half2*)&xhh[(size_t)s_src[i] * 256 + 2 * t];
        float c = s_co[i * 4 + h];
        float2 f = __half22float2(u);
        acc0 += f.x * c;
        acc1 += f.y * c;
    }

    float v0 = acc0 + bias[2 * t];
    float v1 = acc1 + bias[2 * t + 1];
    if (mode) {
        __nv_bfloat16 h0 = __float2bfloat16_rn(v0);
        __nv_bfloat16 h1b = __float2bfloat16_rn(v1);
        __nv_bfloat16 l0 = __float2bfloat16_rn(v0 - __bfloat162float(h0));
        __nv_bfloat16 l1 = __float2bfloat16_rn(v1 - __bfloat162float(h1b));
        __nv_bfloat162 ph; ph.x = h0; ph.y = h1b;
        __nv_bfloat162 pl; pl.x = l0; pl.y = l1;
        size_t base = (size_t)n * 512;
        ((__nv_bfloat162*)(g_A3 + base))[t] = ph;
        ((__nv_bfloat162*)(g_A3 + base + 256))[t] = pl;
    } else {
        out_f32[(size_t)n * 256 + 2 * t]     = v0;
        out_f32[(size_t)n * 256 + 2 * t + 1] = v1;
    }
}

// ---------------- driver ----------------------------------------------------
extern "C" void kernel_launch(void* const* d_in, const int* in_sizes, int n_in,
                              void* d_out, int out_size)
{
    const float* x      = (const float*)d_in[0];
    const int*   ei     = (const int*)d_in[1];
    const float* eattr  = (const float*)d_in[3];
    const float* eatten = (const float*)d_in[4];
    const float* W1     = (const float*)d_in[5];
    const float* as1    = (const float*)d_in[6];
    const float* ad1    = (const float*)d_in[7];
    const float* We1    = (const float*)d_in[8];
    const float* ae1    = (const float*)d_in[9];
    const float* b1     = (const float*)d_in[10];
    const float* W2     = (const float*)d_in[11];
    const float* as2    = (const float*)d_in[12];
    const float* ad2    = (const float*)d_in[13];
    const float* We2    = (const float*)d_in[14];
    const float* ae2    = (const float*)d_in[15];
    const float* b2     = (const float*)d_in[16];

    const int* src = ei;
    const int* dst = ei + EE;

    float* out    = (float*)d_out;
    float* h_out  = out;
    float* w1_out = out + (size_t)NN * FDIM;
    float* w2_out = w1_out + (size_t)EE * HH;

    __half* xhh = nullptr; __half* xhh2 = nullptr;
    __nv_bfloat16* A3 = nullptr; __nv_bfloat16* B3 = nullptr; __nv_bfloat16* B3b = nullptr;
    float* aekp = nullptr; float* aek2p = nullptr;
    cudaGetSymbolAddress((void**)&xhh, g_xhh);
    cudaGetSymbolAddress((void**)&xhh2, g_xhh2);
    cudaGetSymbolAddress((void**)&A3, g_A3);
    cudaGetSymbolAddress((void**)&B3, g_B3);
    cudaGetSymbolAddress((void**)&B3b, g_B3b);
    cudaGetSymbolAddress((void**)&aekp, g_aek);
    cudaGetSymbolAddress((void**)&aek2p, g_aek2);

    static cudaStream_t s1;
    static cudaEvent_t evRoot, evCsr, evG1, evF1b, evA, evG2a, evG2b, evEnd;
    static bool inited = false;
    if (!inited) {
        cudaStreamCreateWithFlags(&s1, cudaStreamNonBlocking);
        cudaEventCreateWithFlags(&evRoot, cudaEventDisableTiming);
        cudaEventCreateWithFlags(&evCsr,  cudaEventDisableTiming);
        cudaEventCreateWithFlags(&evG1,   cudaEventDisableTiming);
        cudaEventCreateWithFlags(&evF1b,  cudaEventDisableTiming);
        cudaEventCreateWithFlags(&evA,    cudaEventDisableTiming);
        cudaEventCreateWithFlags(&evG2a,  cudaEventDisableTiming);
        cudaEventCreateWithFlags(&evG2b,  cudaEventDisableTiming);
        cudaEventCreateWithFlags(&evEnd,  cudaEventDisableTiming);
        inited = true;
    }

    const int EB = (EE + 255) / 256;

    // fork root
    cudaEventRecord(evRoot, 0);
    cudaStreamWaitEvent(s1, evRoot, 0);

    // main first (submission order chosen so gemm1 lands in the ncu window):
    // submitted kernels: 0=k_cvt1, 1=k_zero(s1), 2=k_fill(s1), 3=k_gemm_mma(gemm1)
    k_cvt1<<<2628, 256>>>(x, W1);
    k_zero<<<(NN + 255) / 256, 256, 0, s1>>>(We1, ae1, We2, ae2);
    k_fill<<<EB, 256, 0, s1>>>(dst, src, eattr, eatten);
    cudaEventRecord(evCsr, s1);
    k_gemm_mma<<<dim3(2, 157), 256>>>(A3, B3, xhh, 128, 2, 0, as1, ad1);
    cudaEventRecord(evG1, 0);
    k_cvtW<<<(256 * 256 + 255) / 256, 256, 0, s1>>>(W2, 256, B3b);

    // layer-1 edge phase, split across streams
    cudaStreamWaitEvent(0, evCsr, 0);
    k_fsm<<<2528, 128>>>(w1_out, aekp, 0);               // nodes [0, 10112)
    cudaStreamWaitEvent(s1, evG1, 0);
    k_fsm<<<2472, 128, 0, s1>>>(w1_out, aekp, NHALF_ROWS);  // nodes [10112, 20000)
    cudaEventRecord(evF1b, s1);

    // agg1a; gemm2a on s1 overlaps agg1b
    k_agg16<<<NHALF_ROWS, 128>>>(xhh, b1, nullptr, 1, 0);
    cudaEventRecord(evA, 0);
    cudaStreamWaitEvent(s1, evA, 0);
    k_gemm_mma<<<dim3(2, 79), 256, 0, s1>>>(A3, B3b, xhh2, 256, 3, 0, as2, ad2);
    cudaEventRecord(evG2a, s1);

    cudaStreamWaitEvent(0, evF1b, 0);
    k_agg16<<<NN - NHALF_ROWS, 128>>>(xhh, b1, nullptr, 1, NHALF_ROWS);
    k_gemm_mma<<<dim3(2, 78), 256>>>(A3, B3b, xhh2, 256, 3, NHALF_ROWS, as2, ad2);
    cudaEventRecord(evG2b, 0);

    // layer-2 tail: halves split across streams
    cudaStreamWaitEvent(s1, evG2b, 0);
    k_fsm<<<2500, 128, 0, s1>>>(w2_out, aek2p, 10000);
    k_agg16<<<10000, 128, 0, s1>>>(xhh2, b2, h_out, 0, 10000);
    cudaEventRecord(evEnd, s1);

    cudaStreamWaitEvent(0, evG2a, 0);
    k_fsm<<<2500, 128>>>(w2_out, aek2p, 0);
    k_agg16<<<10000, 128>>>(xhh2, b2, h_out, 0, 0);
    cudaStreamWaitEvent(0, evEnd, 0);
}